// round 15
// baseline (speedup 1.0000x reference)
#include <cuda_runtime.h>
#include <math_constants.h>

#define N_DIM 512
#define KCH 32            // k-chunk per tile pass
#define NCHUNK (N_DIM / KCH)
#define PITCH 33          // conflict-free for scatter, compute, and gather
#define WPB 8             // warps per block
#define NBLK 592          // 4 * 148: every block resident -> spin barrier safe

// Device-global scratch (no allocations allowed). Partials are fully
// overwritten every call; the ticket is monotonic across graph replays.
__device__ float g_pmn[NBLK];
__device__ float g_pmx[NBLK];
__device__ unsigned long long g_ticket;   // zero-init once at module load

// Balanced contiguous split of G groups over nb blocks.
__device__ __forceinline__ void block_span(int G, int b, int nb,
                                           int& strt, int& cnt) {
    int base = G / nb, rem = G % nb;
    cnt  = base + (b < rem);
    strt = b * base + min(b, rem);
}

__global__ void __launch_bounds__(WPB * 32, 4) fused_kernel(
        const float* __restrict__ in,
        const float* __restrict__ alpha,
        const float* __restrict__ beta,
        float* __restrict__ out,
        int rows) {
    __shared__ float tile_s[WPB][32 * PITCH];
    __shared__ float s_red[2 * WPB];
    __shared__ float s_mn, s_mx;

    const int tid  = threadIdx.x;
    const int lane = tid & 31;
    const int warp = tid >> 5;

    const int G = rows >> 5;
    int strt, cnt;
    block_span(G, blockIdx.x, gridDim.x, strt, cnt);

    const int my_col4x4 = (lane & 7) * 4;   // float4 I/O pattern
    const int row_off   = lane >> 3;        // lanes 0-7 = one row's 128B

    const bool active = (warp < cnt);
    const int wgid = strt + (active ? warp : 0);
    const float* __restrict__ inw  = in  + (size_t)wgid * 32 * N_DIM;
    float* __restrict__       outw = out + (size_t)wgid * 32 * N_DIM;

    // ---------------- Phase A: block-local min/max ----------------
    {
        float mn0 =  CUDART_INF_F, mn1 =  CUDART_INF_F;
        float mx0 = -CUDART_INF_F, mx1 = -CUDART_INF_F;
        if (active) {
            // two chunks per iteration -> 16 LDG.128 in flight; still
            // k-descending overall so low-k data is L2/L1-hot at the end.
            #pragma unroll 1
            for (int c2 = NCHUNK - 2; c2 >= 0; c2 -= 2) {
                const int kA = (c2 + 1) * KCH;
                const int kB = c2 * KCH;
                float4 va[8], vb[8];
                #pragma unroll
                for (int t = 0; t < 8; t++) {
                    int r = t * 4 + row_off;
                    va[t] = *(const float4*)(inw + (size_t)r * N_DIM + kA + my_col4x4);
                    vb[t] = *(const float4*)(inw + (size_t)r * N_DIM + kB + my_col4x4);
                }
                #pragma unroll
                for (int t = 0; t < 8; t++) {
                    mn0 = fminf(mn0, fminf(fminf(va[t].x, va[t].y), fminf(va[t].z, va[t].w)));
                    mx0 = fmaxf(mx0, fmaxf(fmaxf(va[t].x, va[t].y), fmaxf(va[t].z, va[t].w)));
                    mn1 = fminf(mn1, fminf(fminf(vb[t].x, vb[t].y), fminf(vb[t].z, vb[t].w)));
                    mx1 = fmaxf(mx1, fmaxf(fmaxf(vb[t].x, vb[t].y), fmaxf(vb[t].z, vb[t].w)));
                }
            }
        }
        float mn = fminf(mn0, mn1);
        float mx = fmaxf(mx0, mx1);
        #pragma unroll
        for (int o = 16; o > 0; o >>= 1) {
            mn = fminf(mn, __shfl_xor_sync(0xFFFFFFFFu, mn, o));
            mx = fmaxf(mx, __shfl_xor_sync(0xFFFFFFFFu, mx, o));
        }
        if (lane == 0) { s_red[warp] = mn; s_red[WPB + warp] = mx; }
        __syncthreads();
        if (tid == 0) {
            float bmn = s_red[0], bmx = s_red[WPB];
            #pragma unroll
            for (int k = 1; k < WPB; k++) {
                bmn = fminf(bmn, s_red[k]);
                bmx = fmaxf(bmx, s_red[WPB + k]);
            }
            g_pmn[blockIdx.x] = bmn;
            g_pmx[blockIdx.x] = bmx;
            __threadfence();                               // publish partials
        }
    }

    // ---- Pre-barrier prefetch: chunk 0 for phase B (input-only; safe).
    float4 q[8];
    if (active) {
        #pragma unroll
        for (int t = 0; t < 8; t++) {
            int r = t * 4 + row_off;
            q[t] = *(const float4*)(inw + (size_t)r * N_DIM + my_col4x4);
        }
    }

    // ---- Global barrier: monotonic ticket (all NBLK blocks co-resident) ----
    if (tid == 0) {
        unsigned long long ret = atomicAdd(&g_ticket, 1ULL);
        unsigned long long target = ret - (ret % NBLK) + NBLK;
        volatile unsigned long long* tk = &g_ticket;
        while (*tk < target) __nanosleep(200);
    }
    __syncthreads();
    __threadfence();                                       // acquire partials

    // ---------------- Reduce all partials (per block) ----------------
    {
        float mn =  CUDART_INF_F;
        float mx = -CUDART_INF_F;
        for (int i = tid; i < NBLK; i += WPB * 32) {
            mn = fminf(mn, g_pmn[i]);
            mx = fmaxf(mx, g_pmx[i]);
        }
        #pragma unroll
        for (int o = 16; o > 0; o >>= 1) {
            mn = fminf(mn, __shfl_xor_sync(0xFFFFFFFFu, mn, o));
            mx = fmaxf(mx, __shfl_xor_sync(0xFFFFFFFFu, mx, o));
        }
        if (lane == 0) { s_red[warp] = mn; s_red[WPB + warp] = mx; }
        __syncthreads();
        if (tid == 0) {
            float bmn = s_red[0], bmx = s_red[WPB];
            #pragma unroll
            for (int k = 1; k < WPB; k++) {
                bmn = fminf(bmn, s_red[k]);
                bmx = fmaxf(bmx, s_red[WPB + k]);
            }
            s_mn = bmn; s_mx = bmx;
        }
        __syncthreads();
    }

    // ---------------- Phase B: warp-tiled recurrence ----------------
    if (!active) return;

    float* tile = tile_s[warp];

    const float mn  = s_mn;
    const float rng = __fsub_rn(s_mx, mn);
    const float inv = __fdiv_rn(1.0f, rng);   // == div-by-rng bitwise (verified R2/R3)
    const float a   = alpha[0];
    const float nb  = -beta[0];

    #define NORM4(v) do {                                     \
        (v).x = __fmul_rn(__fsub_rn((v).x, mn), inv);          \
        (v).y = __fmul_rn(__fsub_rn((v).y, mn), inv);          \
        (v).z = __fmul_rn(__fsub_rn((v).z, mn), inv);          \
        (v).w = __fmul_rn(__fsub_rn((v).w, mn), inv);          \
    } while (0)

    float w = 1.0f;
    float* myrow = tile + lane * PITCH;

    #pragma unroll 1
    for (int c = 0; c < NCHUNK; c++) {
        // Normalize + scatter current chunk -> smem (conflict-free, pitch 33).
        #pragma unroll
        for (int t = 0; t < 8; t++) {
            int r = t * 4 + row_off;
            float4 v = q[t];
            NORM4(v);
            float* p = tile + r * PITCH + my_col4x4;
            p[0] = v.x; p[1] = v.y; p[2] = v.z; p[3] = v.w;
        }
        __syncwarp();

        // Issue next chunk's LDG.128s; they overlap the compute below.
        // (last iteration: re-issue chunk 0 addresses, L1-hot, discarded —
        //  keeps the batch unconditional)
        {
            const int k0n = (c + 1 < NCHUNK) ? (c + 1) * KCH : 0;
            #pragma unroll
            for (int t = 0; t < 8; t++) {
                int r = t * 4 + row_off;
                q[t] = *(const float4*)(inw + (size_t)r * N_DIM + k0n + my_col4x4);
            }
        }

        // Serial recurrence, software-pipelined xn: read xn[kk+1] BEFORE the
        // w-store to slot kk, so the LDS is off the w dependency chain.
        //   w' = fma(-b, xn, w + (a / w)) ; out[:,k] is the pre-step w.
        {
            float xn = myrow[0];
            #pragma unroll
            for (int kk = 0; kk < KCH; kk++) {
                float xn_next = (kk + 1 < KCH) ? myrow[kk + 1] : 0.0f;
                myrow[kk] = w;
                w = __fmaf_rn(nb, xn, __fadd_rn(w, __fdiv_rn(a, w)));
                xn = xn_next;
            }
        }
        __syncwarp();

        // Gather w values from smem and store as STG.128 (coalesced).
        const int k0 = c * KCH;
        #pragma unroll
        for (int t = 0; t < 8; t++) {
            int r = t * 4 + row_off;
            const float* p = tile + r * PITCH + my_col4x4;
            float4 o;
            o.x = p[0]; o.y = p[1]; o.z = p[2]; o.w = p[3];
            *(float4*)(outw + (size_t)r * N_DIM + k0 + my_col4x4) = o;
        }
        __syncwarp();
    }
    #undef NORM4
}

extern "C" void kernel_launch(void* const* d_in, const int* in_sizes, int n_in,
                              void* d_out, int out_size) {
    const float* in    = (const float*)d_in[0];
    const float* alpha = (const float*)d_in[1];
    const float* beta  = (const float*)d_in[2];
    float* out = (float*)d_out;

    long long n_elems = (long long)in_sizes[0];
    int rows = (int)(n_elems / N_DIM);

    fused_kernel<<<NBLK, WPB * 32>>>(in, alpha, beta, out, rows);
}

// round 16
// speedup vs baseline: 1.0171x; 1.0171x over previous
#include <cuda_runtime.h>
#include <math_constants.h>

#define N_DIM 512
#define KCH 32            // k-chunk per tile pass
#define NCHUNK (N_DIM / KCH)
#define PITCH 33          // conflict-free for scatter, compute, and gather
#define WPB 8             // warps per block
#define NBLK 592          // 4 * 148: every block resident -> spin barrier safe
#define KEEP_C 6          // chunks c < KEEP_C cached normally (96MB <= L2)

// Device-global scratch (no allocations allowed). Partials are fully
// overwritten every call; the ticket is monotonic across graph replays.
__device__ float g_pmn[NBLK];
__device__ float g_pmx[NBLK];
__device__ unsigned long long g_ticket;   // zero-init once at module load

// Balanced contiguous split of G groups over nb blocks.
__device__ __forceinline__ void block_span(int G, int b, int nb,
                                           int& strt, int& cnt) {
    int base = G / nb, rem = G % nb;
    cnt  = base + (b < rem);
    strt = b * base + min(b, rem);
}

__global__ void __launch_bounds__(WPB * 32, 4) fused_kernel(
        const float* __restrict__ in,
        const float* __restrict__ alpha,
        const float* __restrict__ beta,
        float* __restrict__ out,
        int rows) {
    __shared__ float tile_s[WPB][32 * PITCH];
    __shared__ float s_red[2 * WPB];
    __shared__ float s_mn, s_mx;

    const int tid  = threadIdx.x;
    const int lane = tid & 31;
    const int warp = tid >> 5;

    const int G = rows >> 5;
    int strt, cnt;
    block_span(G, blockIdx.x, gridDim.x, strt, cnt);

    const int my_col4x4 = (lane & 7) * 4;   // float4 I/O pattern
    const int row_off   = lane >> 3;        // lanes 0-7 = one row's 128B

    const bool active = (warp < cnt);
    const int wgid = strt + (active ? warp : 0);
    const float* __restrict__ inw  = in  + (size_t)wgid * 32 * N_DIM;
    float* __restrict__       outw = out + (size_t)wgid * 32 * N_DIM;

    // ---------------- Phase A: block-local min/max ----------------
    // Chunk-granular stripe over ALL 8 warps (f = c*cnt + gi, descending so
    // k descends overall). c >= KEEP_C loads are evict-first (__ldcs); the
    // low-k chunks (c < KEEP_C, 96MB chip-wide) use default policy and thus
    // survive in L2 for phase B's ascending sweep.
    {
        float mn0 =  CUDART_INF_F, mn1 =  CUDART_INF_F;
        float mx0 = -CUDART_INF_F, mx1 = -CUDART_INF_F;
        const int totalChunks = cnt * NCHUNK;

        #define CHUNK_LOAD(fidx, vv) do {                                     \
            int c_  = (fidx) / cnt;                                            \
            int gi_ = (fidx) - c_ * cnt;                                       \
            const float* gp_ = in + (size_t)(strt + gi_) * 32 * N_DIM          \
                                  + c_ * KCH + my_col4x4;                      \
            if (c_ >= KEEP_C) {                                                \
                _Pragma("unroll")                                              \
                for (int t = 0; t < 8; t++)                                    \
                    (vv)[t] = __ldcs((const float4*)(gp_ + (size_t)(t*4+row_off)*N_DIM)); \
            } else {                                                           \
                _Pragma("unroll")                                              \
                for (int t = 0; t < 8; t++)                                    \
                    (vv)[t] = *(const float4*)(gp_ + (size_t)(t*4+row_off)*N_DIM); \
            } } while (0)

        #define RED8(vv, MN, MX) do {                                          \
            _Pragma("unroll")                                                   \
            for (int t = 0; t < 8; t++) {                                       \
                MN = fminf(MN, fminf(fminf((vv)[t].x, (vv)[t].y),               \
                                     fminf((vv)[t].z, (vv)[t].w)));             \
                MX = fmaxf(MX, fmaxf(fmaxf((vv)[t].x, (vv)[t].y),               \
                                     fmaxf((vv)[t].z, (vv)[t].w)));             \
            } } while (0)

        int f = totalChunks - 1 - warp;
        for (; f - WPB >= 0; f -= 2 * WPB) {       // pairs: 16 LDG.128 in flight
            float4 va[8], vb[8];
            CHUNK_LOAD(f, va);
            CHUNK_LOAD(f - WPB, vb);
            RED8(va, mn0, mx0);
            RED8(vb, mn1, mx1);
        }
        if (f >= 0) {
            float4 va[8];
            CHUNK_LOAD(f, va);
            RED8(va, mn0, mx0);
        }
        #undef CHUNK_LOAD
        #undef RED8

        float mn = fminf(mn0, mn1);
        float mx = fmaxf(mx0, mx1);
        #pragma unroll
        for (int o = 16; o > 0; o >>= 1) {
            mn = fminf(mn, __shfl_xor_sync(0xFFFFFFFFu, mn, o));
            mx = fmaxf(mx, __shfl_xor_sync(0xFFFFFFFFu, mx, o));
        }
        if (lane == 0) { s_red[warp] = mn; s_red[WPB + warp] = mx; }
        __syncthreads();
        if (tid == 0) {
            float bmn = s_red[0], bmx = s_red[WPB];
            #pragma unroll
            for (int k = 1; k < WPB; k++) {
                bmn = fminf(bmn, s_red[k]);
                bmx = fmaxf(bmx, s_red[WPB + k]);
            }
            g_pmn[blockIdx.x] = bmn;
            g_pmx[blockIdx.x] = bmx;
            __threadfence();                               // publish partials
        }
    }

    // ---- Pre-barrier prefetch: chunk 0 for phase B (input-only; L2-hot).
    float4 q[8];
    if (active) {
        #pragma unroll
        for (int t = 0; t < 8; t++) {
            int r = t * 4 + row_off;
            q[t] = __ldcs((const float4*)(inw + (size_t)r * N_DIM + my_col4x4));
        }
    }

    // ---- Global barrier: monotonic ticket (all NBLK blocks co-resident) ----
    if (tid == 0) {
        unsigned long long ret = atomicAdd(&g_ticket, 1ULL);
        unsigned long long target = ret - (ret % NBLK) + NBLK;
        volatile unsigned long long* tk = &g_ticket;
        while (*tk < target) __nanosleep(200);
    }
    __syncthreads();
    __threadfence();                                       // acquire partials

    // ---------------- Reduce all partials (per block) ----------------
    {
        float mn =  CUDART_INF_F;
        float mx = -CUDART_INF_F;
        for (int i = tid; i < NBLK; i += WPB * 32) {
            mn = fminf(mn, g_pmn[i]);
            mx = fmaxf(mx, g_pmx[i]);
        }
        #pragma unroll
        for (int o = 16; o > 0; o >>= 1) {
            mn = fminf(mn, __shfl_xor_sync(0xFFFFFFFFu, mn, o));
            mx = fmaxf(mx, __shfl_xor_sync(0xFFFFFFFFu, mx, o));
        }
        if (lane == 0) { s_red[warp] = mn; s_red[WPB + warp] = mx; }
        __syncthreads();
        if (tid == 0) {
            float bmn = s_red[0], bmx = s_red[WPB];
            #pragma unroll
            for (int k = 1; k < WPB; k++) {
                bmn = fminf(bmn, s_red[k]);
                bmx = fmaxf(bmx, s_red[WPB + k]);
            }
            s_mn = bmn; s_mx = bmx;
        }
        __syncthreads();
    }

    // ---------------- Phase B: warp-tiled recurrence ----------------
    if (!active) return;

    float* tile = tile_s[warp];

    const float mn  = s_mn;
    const float rng = __fsub_rn(s_mx, mn);
    const float inv = __fdiv_rn(1.0f, rng);   // == div-by-rng bitwise (verified R2/R3)
    const float a   = alpha[0];
    const float nb  = -beta[0];

    #define NORM4(v) do {                                     \
        (v).x = __fmul_rn(__fsub_rn((v).x, mn), inv);          \
        (v).y = __fmul_rn(__fsub_rn((v).y, mn), inv);          \
        (v).z = __fmul_rn(__fsub_rn((v).z, mn), inv);          \
        (v).w = __fmul_rn(__fsub_rn((v).w, mn), inv);          \
    } while (0)

    float w = 1.0f;
    float* myrow = tile + lane * PITCH;

    #pragma unroll 1
    for (int c = 0; c < NCHUNK; c++) {
        // Normalize + scatter current chunk -> smem (conflict-free, pitch 33).
        #pragma unroll
        for (int t = 0; t < 8; t++) {
            int r = t * 4 + row_off;
            float4 v = q[t];
            NORM4(v);
            float* p = tile + r * PITCH + my_col4x4;
            p[0] = v.x; p[1] = v.y; p[2] = v.z; p[3] = v.w;
        }
        __syncwarp();

        // Issue next chunk's LDG.128s (evict-first: last use); overlap compute.
        if (c + 1 < NCHUNK) {
            const int k0n = (c + 1) * KCH;
            #pragma unroll
            for (int t = 0; t < 8; t++) {
                int r = t * 4 + row_off;
                q[t] = __ldcs((const float4*)(inw + (size_t)r * N_DIM + k0n + my_col4x4));
            }
        }

        // Serial recurrence: lane = row; tile holds pre-normalized xn.
        //   w' = fma(-b, xn, w + (a / w)) ; out[:,k] is the pre-step w.
        #pragma unroll
        for (int kk = 0; kk < KCH; kk++) {
            float xn = myrow[kk];
            myrow[kk] = w;
            w = __fmaf_rn(nb, xn, __fadd_rn(w, __fdiv_rn(a, w)));
        }
        __syncwarp();

        // Gather w values and store as STG.128 evict-first (never re-read).
        const int k0 = c * KCH;
        #pragma unroll
        for (int t = 0; t < 8; t++) {
            int r = t * 4 + row_off;
            const float* p = tile + r * PITCH + my_col4x4;
            float4 o;
            o.x = p[0]; o.y = p[1]; o.z = p[2]; o.w = p[3];
            __stcs((float4*)(outw + (size_t)r * N_DIM + k0 + my_col4x4), o);
        }
        __syncwarp();
    }
    #undef NORM4
}

extern "C" void kernel_launch(void* const* d_in, const int* in_sizes, int n_in,
                              void* d_out, int out_size) {
    const float* in    = (const float*)d_in[0];
    const float* alpha = (const float*)d_in[1];
    const float* beta  = (const float*)d_in[2];
    float* out = (float*)d_out;

    long long n_elems = (long long)in_sizes[0];
    int rows = (int)(n_elems / N_DIM);

    fused_kernel<<<NBLK, WPB * 32>>>(in, alpha, beta, out, rows);
}

// round 17
// speedup vs baseline: 1.0561x; 1.0383x over previous
#include <cuda_runtime.h>
#include <math_constants.h>

#define N_DIM 512
#define KCH 32            // k-chunk per tile pass
#define NCHUNK (N_DIM / KCH)
#define PITCH 33          // conflict-free for scatter, compute, and gather
#define WPB 8             // warps per block
#define NBLK 592          // 4 * 148: every block resident -> spin barrier safe
#define KEEP_C 7          // chunks c < KEEP_C cached normally (112MB <= L2)

// Device-global scratch (no allocations allowed). Partials are fully
// overwritten every call; the ticket is monotonic across graph replays.
__device__ float g_pmn[NBLK];
__device__ float g_pmx[NBLK];
__device__ unsigned long long g_ticket;   // zero-init once at module load

// Balanced contiguous split of G groups over nb blocks.
__device__ __forceinline__ void block_span(int G, int b, int nb,
                                           int& strt, int& cnt) {
    int base = G / nb, rem = G % nb;
    cnt  = base + (b < rem);
    strt = b * base + min(b, rem);
}

__global__ void __launch_bounds__(WPB * 32, 4) fused_kernel(
        const float* __restrict__ in,
        const float* __restrict__ alpha,
        const float* __restrict__ beta,
        float* __restrict__ out,
        int rows) {
    __shared__ float tile_s[WPB][32 * PITCH];
    __shared__ float s_red[2 * WPB];
    __shared__ float s_mn, s_mx;

    const int tid  = threadIdx.x;
    const int lane = tid & 31;
    const int warp = tid >> 5;

    const int G = rows >> 5;
    int strt, cnt;
    block_span(G, blockIdx.x, gridDim.x, strt, cnt);

    const int my_col4x4 = (lane & 7) * 4;   // float4 I/O pattern
    const int row_off   = lane >> 3;        // lanes 0-7 = one row's 128B

    const bool active = (warp < cnt);
    const int wgid = strt + (active ? warp : 0);
    const float* __restrict__ inw  = in  + (size_t)wgid * 32 * N_DIM;
    float* __restrict__       outw = out + (size_t)wgid * 32 * N_DIM;

    // ---------------- Phase A: block-local min/max ----------------
    // R14 shape: per-warp group ownership, TWO chunks per iteration
    // (16 LDG.128 in flight), k-descending. R16 policy: high-k chunks
    // (c >= KEEP_C) loaded evict-first so the low-k chunks (112MB chip-wide)
    // survive in L2 for phase B's ascending sweep.
    {
        float mn0 =  CUDART_INF_F, mn1 =  CUDART_INF_F;
        float mx0 = -CUDART_INF_F, mx1 = -CUDART_INF_F;
        if (active) {
            #pragma unroll 1
            for (int c2 = NCHUNK - 2; c2 >= 0; c2 -= 2) {
                const int cA = c2 + 1;
                const int cB = c2;
                const int kA = cA * KCH;
                const int kB = cB * KCH;
                float4 va[8], vb[8];
                if (cA >= KEEP_C) {          // warp-uniform branch
                    #pragma unroll
                    for (int t = 0; t < 8; t++) {
                        int r = t * 4 + row_off;
                        va[t] = __ldcs((const float4*)(inw + (size_t)r * N_DIM + kA + my_col4x4));
                    }
                } else {
                    #pragma unroll
                    for (int t = 0; t < 8; t++) {
                        int r = t * 4 + row_off;
                        va[t] = *(const float4*)(inw + (size_t)r * N_DIM + kA + my_col4x4);
                    }
                }
                if (cB >= KEEP_C) {
                    #pragma unroll
                    for (int t = 0; t < 8; t++) {
                        int r = t * 4 + row_off;
                        vb[t] = __ldcs((const float4*)(inw + (size_t)r * N_DIM + kB + my_col4x4));
                    }
                } else {
                    #pragma unroll
                    for (int t = 0; t < 8; t++) {
                        int r = t * 4 + row_off;
                        vb[t] = *(const float4*)(inw + (size_t)r * N_DIM + kB + my_col4x4);
                    }
                }
                #pragma unroll
                for (int t = 0; t < 8; t++) {
                    mn0 = fminf(mn0, fminf(fminf(va[t].x, va[t].y), fminf(va[t].z, va[t].w)));
                    mx0 = fmaxf(mx0, fmaxf(fmaxf(va[t].x, va[t].y), fmaxf(va[t].z, va[t].w)));
                    mn1 = fminf(mn1, fminf(fminf(vb[t].x, vb[t].y), fminf(vb[t].z, vb[t].w)));
                    mx1 = fmaxf(mx1, fmaxf(fmaxf(vb[t].x, vb[t].y), fmaxf(vb[t].z, vb[t].w)));
                }
            }
        }
        float mn = fminf(mn0, mn1);
        float mx = fmaxf(mx0, mx1);
        #pragma unroll
        for (int o = 16; o > 0; o >>= 1) {
            mn = fminf(mn, __shfl_xor_sync(0xFFFFFFFFu, mn, o));
            mx = fmaxf(mx, __shfl_xor_sync(0xFFFFFFFFu, mx, o));
        }
        if (lane == 0) { s_red[warp] = mn; s_red[WPB + warp] = mx; }
        __syncthreads();
        if (tid == 0) {
            float bmn = s_red[0], bmx = s_red[WPB];
            #pragma unroll
            for (int k = 1; k < WPB; k++) {
                bmn = fminf(bmn, s_red[k]);
                bmx = fmaxf(bmx, s_red[WPB + k]);
            }
            g_pmn[blockIdx.x] = bmn;
            g_pmx[blockIdx.x] = bmx;
            __threadfence();                               // publish partials
        }
    }

    // ---- Pre-barrier prefetch: chunk 0 for phase B (input-only; L2-hot).
    float4 q[8];
    if (active) {
        #pragma unroll
        for (int t = 0; t < 8; t++) {
            int r = t * 4 + row_off;
            q[t] = __ldcs((const float4*)(inw + (size_t)r * N_DIM + my_col4x4));
        }
    }

    // ---- Global barrier: monotonic ticket (all NBLK blocks co-resident) ----
    if (tid == 0) {
        unsigned long long ret = atomicAdd(&g_ticket, 1ULL);
        unsigned long long target = ret - (ret % NBLK) + NBLK;
        volatile unsigned long long* tk = &g_ticket;
        while (*tk < target) __nanosleep(200);
    }
    __syncthreads();
    __threadfence();                                       // acquire partials

    // ---------------- Reduce all partials (per block) ----------------
    {
        float mn =  CUDART_INF_F;
        float mx = -CUDART_INF_F;
        for (int i = tid; i < NBLK; i += WPB * 32) {
            mn = fminf(mn, g_pmn[i]);
            mx = fmaxf(mx, g_pmx[i]);
        }
        #pragma unroll
        for (int o = 16; o > 0; o >>= 1) {
            mn = fminf(mn, __shfl_xor_sync(0xFFFFFFFFu, mn, o));
            mx = fmaxf(mx, __shfl_xor_sync(0xFFFFFFFFu, mx, o));
        }
        if (lane == 0) { s_red[warp] = mn; s_red[WPB + warp] = mx; }
        __syncthreads();
        if (tid == 0) {
            float bmn = s_red[0], bmx = s_red[WPB];
            #pragma unroll
            for (int k = 1; k < WPB; k++) {
                bmn = fminf(bmn, s_red[k]);
                bmx = fmaxf(bmx, s_red[WPB + k]);
            }
            s_mn = bmn; s_mx = bmx;
        }
        __syncthreads();
    }

    // ---------------- Phase B: warp-tiled recurrence ----------------
    if (!active) return;

    float* tile = tile_s[warp];

    const float mn  = s_mn;
    const float rng = __fsub_rn(s_mx, mn);
    const float inv = __fdiv_rn(1.0f, rng);   // == div-by-rng bitwise (verified R2/R3)
    const float a   = alpha[0];
    const float nb  = -beta[0];

    #define NORM4(v) do {                                     \
        (v).x = __fmul_rn(__fsub_rn((v).x, mn), inv);          \
        (v).y = __fmul_rn(__fsub_rn((v).y, mn), inv);          \
        (v).z = __fmul_rn(__fsub_rn((v).z, mn), inv);          \
        (v).w = __fmul_rn(__fsub_rn((v).w, mn), inv);          \
    } while (0)

    float w = 1.0f;
    float* myrow = tile + lane * PITCH;

    #pragma unroll 1
    for (int c = 0; c < NCHUNK; c++) {
        // Normalize + scatter current chunk -> smem (conflict-free, pitch 33).
        #pragma unroll
        for (int t = 0; t < 8; t++) {
            int r = t * 4 + row_off;
            float4 v = q[t];
            NORM4(v);
            float* p = tile + r * PITCH + my_col4x4;
            p[0] = v.x; p[1] = v.y; p[2] = v.z; p[3] = v.w;
        }
        __syncwarp();

        // Issue next chunk's LDG.128s (evict-first: last use); overlap compute.
        if (c + 1 < NCHUNK) {
            const int k0n = (c + 1) * KCH;
            #pragma unroll
            for (int t = 0; t < 8; t++) {
                int r = t * 4 + row_off;
                q[t] = __ldcs((const float4*)(inw + (size_t)r * N_DIM + k0n + my_col4x4));
            }
        }

        // Serial recurrence: lane = row; tile holds pre-normalized xn.
        //   w' = fma(-b, xn, w + (a / w)) ; out[:,k] is the pre-step w.
        #pragma unroll
        for (int kk = 0; kk < KCH; kk++) {
            float xn = myrow[kk];
            myrow[kk] = w;
            w = __fmaf_rn(nb, xn, __fadd_rn(w, __fdiv_rn(a, w)));
        }
        __syncwarp();

        // Gather w values and store as STG.128 evict-first (never re-read).
        const int k0 = c * KCH;
        #pragma unroll
        for (int t = 0; t < 8; t++) {
            int r = t * 4 + row_off;
            const float* p = tile + r * PITCH + my_col4x4;
            float4 o;
            o.x = p[0]; o.y = p[1]; o.z = p[2]; o.w = p[3];
            __stcs((float4*)(outw + (size_t)r * N_DIM + k0 + my_col4x4), o);
        }
        __syncwarp();
    }
    #undef NORM4
}

extern "C" void kernel_launch(void* const* d_in, const int* in_sizes, int n_in,
                              void* d_out, int out_size) {
    const float* in    = (const float*)d_in[0];
    const float* alpha = (const float*)d_in[1];
    const float* beta  = (const float*)d_in[2];
    float* out = (float*)d_out;

    long long n_elems = (long long)in_sizes[0];
    int rows = (int)(n_elems / N_DIM);

    fused_kernel<<<NBLK, WPB * 32>>>(in, alpha, beta, out, rows);
}